// round 7
// baseline (speedup 1.0000x reference)
#include <cuda_runtime.h>
#include <cuda_bf16.h>
#include <cstdint>

// Problem constants (fixed by setup_inputs)
#define B_   8
#define NS   5
#define NQ   128
#define T_   16
#define D_   2048
#define NROWS (B_*NQ)           // 1024

__device__ float g_rowterm[NROWS];
__device__ unsigned int g_done;   // zero-init; last block resets

#define LAM 0.1f
#define INVLAM 10.0f

__device__ __forceinline__ float softmin2(float a, float b) {
    float mn = fminf(a, b);
    return mn - LAM * __logf(1.0f + __expf(-fabsf(a - b) * INVLAM));
}
__device__ __forceinline__ float softmin3(float a, float b, float c) {
    float mn = fminf(fminf(a, b), c);
    float s = __expf((mn - a) * INVLAM) + __expf((mn - b) * INVLAM) + __expf((mn - c) * INVLAM);
    return mn - LAM * __logf(s);
}

__device__ __forceinline__ uint32_t smem_u32(const void* p) {
    uint32_t a;
    asm("{ .reg .u64 t; cvta.to.shared.u64 t, %1; cvt.u32.u64 %0, t; }" : "=r"(a) : "l"(p));
    return a;
}
__device__ __forceinline__ void ldsm4(uint32_t addr, uint32_t& r0, uint32_t& r1,
                                      uint32_t& r2, uint32_t& r3) {
    asm volatile("ldmatrix.sync.aligned.m8n8.x4.shared.b16 {%0,%1,%2,%3}, [%4];"
                 : "=r"(r0), "=r"(r1), "=r"(r2), "=r"(r3) : "r"(addr));
}
// f32x4 -> packed bf16x4 (two u32)
__device__ __forceinline__ uint2 cvt_u2(float4 v) {
    union { __nv_bfloat162 h; uint32_t u; } lo, hi;
    lo.h = __floats2bfloat162_rn(v.x, v.y);
    hi.h = __floats2bfloat162_rn(v.z, v.w);
    return make_uint2(lo.u, hi.u);
}

// ---------------- fused kernel ----------------
// Block: batch b x 128 query rows. 4 groups of 160 threads:
//   gid = (kg, nh): kg = K-half split, nh = 64-query-row N-half.
// Each group: private double-buffered A(80x40) + B(64x40) bf16 tiles, own named barrier.
#define BM 80
#define BK 32          // f32 per chunk
#define LDA 40         // smem row stride in bf16 (80 B)
#define GT 640
#define PSTRIDE 257

#define AB_G 6400              // 80*40*2
#define BB_G 5120              // 64*40*2
#define STAGE_G 11520          // AB_G + BB_G
#define GROUP_BYTES 23040      // 2 stages
#define TILES_BYTES 92160      // 4 groups

#define OFF_ACC  TILES_BYTES               // accbuf / sDist (f32), 10560 f32
#define ACCBUF_F 10560
#define OFF_QSUM (OFF_ACC + ACCBUF_F*4)    // [2][128] f32
#define OFF_SSUM (OFF_QSUM + 256*4)        // [2][80] f32
#define OFF_T1   (OFF_SSUM + 160*4)        // [40]
#define OFF_T2   (OFF_T1 + 40*4)           // [40]
#define SMEM_BYTES (OFF_T2 + 40*4 + 64)

__global__ __launch_bounds__(GT, 1) void gemm_dtw_kernel(
        const float* __restrict__ supp, const float* __restrict__ query,
        const int* __restrict__ ys, float* __restrict__ out) {
    extern __shared__ char smc[];
    float* accbuf = (float*)(smc + OFF_ACC);
    float* sDist  = accbuf;
    float* qsum   = (float*)(smc + OFF_QSUM);
    float* ssum   = (float*)(smc + OFF_SSUM);
    float* t1s    = (float*)(smc + OFF_T1);
    float* t2s    = (float*)(smc + OFF_T2);

    const int b = blockIdx.y, nt = blockIdx.x;
    const int tid = threadIdx.x, wid = tid >> 5, lane = tid & 31;
    const int gid = wid / 5;             // 0..3
    const int kg = gid & 1, nh = gid >> 1;
    const int gw = wid - gid * 5;        // warp in group: M tile
    const int gtid = tid - gid * 160;

    const float* Ag = supp  + (size_t)b * BM * D_;
    const float* Bg = query + ((size_t)b * (NQ*T_) + (size_t)nt * 128) * D_;

    float acc[8][4];
    #pragma unroll
    for (int j = 0; j < 8; j++) { acc[j][0]=0.f; acc[j][1]=0.f; acc[j][2]=0.f; acc[j][3]=0.f; }

    const int g = lane >> 2, t = lane & 3;
    const int quad = lane >> 3, qi = lane & 7;

    // ldmatrix byte offsets within group stage
    const uint32_t smb = smem_u32(smc);
    const uint32_t smbG = smb + gid * GROUP_BYTES;
    const uint32_t offA = (uint32_t)((gw*16 + qi + (quad & 1)*8) * 80 + (quad >> 1) * 16);
    uint32_t offB[4];
    #pragma unroll
    for (int jj = 0; jj < 4; jj++)
        offB[jj] = (uint32_t)(((2*jj + (quad >> 1))*8 + qi) * 80 + (quad & 1) * 16);

    // loader geometry: slot s -> A row r0+20s (s=0..3), B row r0+20s (s=4..7)
    const int r0 = gtid >> 3;                 // 0..19
    const int cb = (gtid & 7) * 4;            // f32 col
    const int cb8 = (gtid & 7) * 8;           // bf16 byte col
    const bool s7ok = (r0 < 4);               // B row r0+60 < 64
    const float* pA = Ag + (size_t)r0 * D_ + cb + kg * BK;
    const float* pB = Bg + (size_t)(nh * 64 + r0) * D_ + cb + kg * BK;
    const int soffA = r0 * 80 + cb8;
    const int soffB = AB_G + r0 * 80 + cb8;
    #define RSTRIDE (20 * D_)

    float4 fa[4], fb[4];
    fb[3].x = fb[3].y = fb[3].z = fb[3].w = 0.f;
    float sqA[4] = {0.f,0.f,0.f,0.f}, sqB[4] = {0.f,0.f,0.f,0.f};
    #define DOT4(v) ((v).x*(v).x + (v).y*(v).y + (v).z*(v).z + (v).w*(v).w)

    #define LOAD_ALL() do { \
        fa[0] = *(const float4*)(pA); \
        fa[1] = *(const float4*)(pA + RSTRIDE); \
        fa[2] = *(const float4*)(pA + 2*RSTRIDE); \
        fa[3] = *(const float4*)(pA + 3*RSTRIDE); \
        fb[0] = *(const float4*)(pB); \
        fb[1] = *(const float4*)(pB + RSTRIDE); \
        fb[2] = *(const float4*)(pB + 2*RSTRIDE); \
        if (s7ok) fb[3] = *(const float4*)(pB + 3*RSTRIDE); \
        pA += 64; pB += 64; } while(0)

    #define SUMSQ_ALL() do { \
        sqA[0] += DOT4(fa[0]); sqA[1] += DOT4(fa[1]); sqA[2] += DOT4(fa[2]); sqA[3] += DOT4(fa[3]); \
        sqB[0] += DOT4(fb[0]); sqB[1] += DOT4(fb[1]); sqB[2] += DOT4(fb[2]); sqB[3] += DOT4(fb[3]); } while(0)

    #define STS_ALL(stage) do { \
        char* st = smc + gid * GROUP_BYTES + (stage) * STAGE_G; \
        *(uint2*)(st + soffA)          = cvt_u2(fa[0]); \
        *(uint2*)(st + soffA + 1600)   = cvt_u2(fa[1]); \
        *(uint2*)(st + soffA + 3200)   = cvt_u2(fa[2]); \
        *(uint2*)(st + soffA + 4800)   = cvt_u2(fa[3]); \
        *(uint2*)(st + soffB)          = cvt_u2(fb[0]); \
        *(uint2*)(st + soffB + 1600)   = cvt_u2(fb[1]); \
        *(uint2*)(st + soffB + 3200)   = cvt_u2(fb[2]); \
        if (s7ok) *(uint2*)(st + soffB + 4800) = cvt_u2(fb[3]); } while(0)

    #define GBAR() asm volatile("bar.sync %0, %1;" :: "r"(gid + 1), "r"(160) : "memory")

    // ---- prologue: chunk 0 of this group ----
    LOAD_ALL();
    SUMSQ_ALL();
    STS_ALL(0);
    GBAR();

    const int NIT = (D_ / BK) / 2;   // 32 chunks per group
    for (int i = 0; i < NIT; i++) {
        const int buf = i & 1;
        const bool more = (i + 1) < NIT;

        if (more) LOAD_ALL();

        // ---- fragment loads + MMAs on buf ----
        const uint32_t aB = smbG + (uint32_t)buf * STAGE_G + offA;
        const uint32_t bB = smbG + (uint32_t)buf * STAGE_G + AB_G;
        #pragma unroll
        for (int ks = 0; ks < 2; ks++) {
            uint32_t a0, a1, a2, a3;
            ldsm4(aB + ks * 32, a0, a1, a2, a3);
            uint32_t bf[16];
            #pragma unroll
            for (int jj = 0; jj < 4; jj++)
                ldsm4(bB + offB[jj] + ks * 32, bf[4*jj], bf[4*jj+1], bf[4*jj+2], bf[4*jj+3]);
            #pragma unroll
            for (int j = 0; j < 8; j++) {
                asm volatile(
                    "mma.sync.aligned.m16n8k16.row.col.f32.bf16.bf16.f32 "
                    "{%0,%1,%2,%3}, {%4,%5,%6,%7}, {%8,%9}, {%0,%1,%2,%3};\n"
                    : "+f"(acc[j][0]), "+f"(acc[j][1]), "+f"(acc[j][2]), "+f"(acc[j][3])
                    : "r"(a0), "r"(a1), "r"(a2), "r"(a3), "r"(bf[2*j]), "r"(bf[2*j+1]));
            }
        }

        if (more) {
            SUMSQ_ALL();
            STS_ALL(buf ^ 1);
        }
        GBAR();
    }

    // ---- per-slot 8-lane deterministic reduction of sum-of-squares ----
    #pragma unroll
    for (int o = 4; o; o >>= 1) {
        #pragma unroll
        for (int s = 0; s < 4; s++) {
            sqA[s] += __shfl_xor_sync(0xffffffffu, sqA[s], o);
            sqB[s] += __shfl_xor_sync(0xffffffffu, sqB[s], o);
        }
    }
    if ((gtid & 7) == 0) {
        if (nh == 0) {
            #pragma unroll
            for (int s = 0; s < 4; s++) ssum[kg*80 + r0 + 20*s] = sqA[s];
        }
        #pragma unroll
        for (int s = 0; s < 3; s++) qsum[kg*128 + nh*64 + r0 + 20*s] = sqB[s];
        if (s7ok) qsum[kg*128 + nh*64 + r0 + 60] = sqB[3];
    }

    // ---- kg=1 groups dump acc (per-nh region, stride-33 conflict-free) ----
    if (kg == 1) {
        float* ab = accbuf + nh * 5280 + gw * 1056 + lane;
        #pragma unroll
        for (int j = 0; j < 8; j++)
            #pragma unroll
            for (int c = 0; c < 4; c++)
                ab[(j*4 + c) * 33] = acc[j][c];
    }
    __syncthreads();

    // ---- kg=0 groups: reduce; combine norms ----
    if (kg == 0) {
        const float* ab = accbuf + nh * 5280 + gw * 1056 + lane;
        #pragma unroll
        for (int j = 0; j < 8; j++)
            #pragma unroll
            for (int c = 0; c < 4; c++)
                acc[j][c] += ab[(j*4 + c) * 33];
    }
    if (tid < 128)      qsum[tid] = rsqrtf(fmaxf(qsum[tid] + qsum[128 + tid], 1e-12f));
    else if (tid < 208) ssum[tid - 128] = rsqrtf(fmaxf(ssum[tid - 128] + ssum[80 + tid - 128], 1e-12f));
    __syncthreads();

    // ---- epilogue: dist into smem (kg=0 groups) ----
    if (kg == 0) {
        #pragma unroll
        for (int j = 0; j < 8; j++) {
            const int lc = nh * 64 + j * 8 + t * 2;
            #pragma unroll
            for (int half = 0; half < 2; half++) {
                const int lr = gw * 16 + g + half * 8;      // 0..79
                const float invs = ssum[lr];
                const int s = lr >> 4, l = lr & 15;
                #pragma unroll
                for (int e = 0; e < 2; e++) {
                    const int c = lc + e;                    // 0..127
                    const int qloc = c >> 4, m = c & 15;
                    const int pb = qloc * NS + s;
                    const float v = acc[j][half * 2 + e];
                    sDist[pb * PSTRIDE + (l << 4) + m] = 1.0f - v * invs * qsum[c];
                }
            }
        }
    }
    __syncthreads();

    // ---- soft-DTW: 80 threads, one (problem, direction) each ----
    if (tid < 80) {
        const int pb = tid >> 1, dir = tid & 1;
        const float* dm = sDist + pb * PSTRIDE;
        const int base = dir ? 255 : 0;
        const int sgn = dir ? -1 : 1;

        float prev[T_ + 2];
        prev[0] = 0.f;
        #pragma unroll
        for (int m = 1; m <= T_; m++) prev[m] = prev[m - 1] + dm[base + sgn * (m - 1)];
        prev[T_ + 1] = prev[T_];

        for (int l = 1; l < T_; l++) {
            const int rb = base + sgn * (l * 16);
            float drow[T_];
            #pragma unroll
            for (int m = 0; m < T_; m++) drow[m] = dm[rb + sgn * m];
            float left = 0.f;
            float dprev = prev[0];
            #pragma unroll
            for (int m = 1; m <= T_ + 1; m++) {
                const float up = prev[m];
                const float d = (m <= T_) ? drow[m - 1] : 0.f;
                float val;
                if (m == 1 || m == T_ + 1) val = softmin3(dprev, left, up) + d;
                else                        val = softmin2(dprev, left) + d;
                dprev = up;
                prev[m] = val;
                left = val;
            }
        }
        if (dir == 0) t1s[pb] = prev[T_ + 1];
        else          t2s[pb] = prev[T_ + 1];
    }
    __syncthreads();

    // ---- per-block outputs: tam + per-query CE term ----
    if (tid < 40) {
        const int qloc = tid / NS, s = tid % NS;
        const int row = b * NQ + nt * 8 + qloc;
        out[1 + row * NS + s] = 0.5f * (t1s[tid] + t2s[tid]);
    }
    if (tid < 8) {
        const int row = b * NQ + nt * 8 + tid;
        float t1[NS], t2[NS];
        #pragma unroll
        for (int s = 0; s < NS; s++) { t1[s] = t1s[tid * NS + s]; t2[s] = t2s[tid * NS + s]; }
        float mx1 = -t1[0], mx2 = -t2[0];
        #pragma unroll
        for (int s = 1; s < NS; s++) { mx1 = fmaxf(mx1, -t1[s]); mx2 = fmaxf(mx2, -t2[s]); }
        float se1 = 0.f, se2 = 0.f;
        #pragma unroll
        for (int s = 0; s < NS; s++) { se1 += __expf(-t1[s] - mx1); se2 += __expf(-t2[s] - mx2); }
        const int y = ys[row];
        g_rowterm[row] = (mx1 + __logf(se1) + t1[y]) + (mx2 + __logf(se2) + t2[y]);
    }

    // ---- last block computes the final loss ----
    __shared__ unsigned s_last;
    __shared__ float s_red[20];
    __threadfence();
    __syncthreads();
    if (tid == 0) s_last = (atomicAdd(&g_done, 1u) == 127u) ? 1u : 0u;
    __syncthreads();
    if (s_last) {
        float v = 0.f;
        if (tid < 512) v = g_rowterm[tid] + g_rowterm[tid + 512];
        #pragma unroll
        for (int o = 16; o; o >>= 1) v += __shfl_xor_sync(0xffffffffu, v, o);
        if (lane == 0 && wid < 16) s_red[wid] = v;
        __syncthreads();
        if (wid == 0) {
            float u = (lane < 16) ? s_red[lane] : 0.f;
            #pragma unroll
            for (int o = 8; o; o >>= 1) u += __shfl_xor_sync(0xffffffffu, u, o);
            if (lane == 0) { out[0] = 0.5f * u / (float)NROWS; g_done = 0u; }
        }
    }
}

// ---------------- launch ----------------
extern "C" void kernel_launch(void* const* d_in, const int* in_sizes, int n_in,
                              void* d_out, int out_size) {
    const float* supp  = (const float*)d_in[0];
    const float* query = (const float*)d_in[1];
    const int*   ys    = (const int*)d_in[2];
    float* out = (float*)d_out;

    static bool attr_set = false;
    if (!attr_set) {
        cudaFuncSetAttribute(gemm_dtw_kernel,
                             cudaFuncAttributeMaxDynamicSharedMemorySize, SMEM_BYTES);
        attr_set = true;
    }

    gemm_dtw_kernel<<<dim3(16, B_), GT, SMEM_BYTES>>>(supp, query, ys, out);
}